// round 6
// baseline (speedup 1.0000x reference)
#include <cuda_runtime.h>

#define B_TOTAL 262144
#define TPB 128
#define ROWS_CTA 256
#define NBLK (B_TOTAL / ROWS_CTA)          // 1024

// smem: Wf[3][64][64] + one staging slot of 256 rows x 64 floats (16B-chunk swizzled)
#define WL 4096
#define W_TOTAL (3 * WL)                   // 12288 floats
#define SLOT_FLOATS (ROWS_CTA * 64)        // 16384 floats
#define SMEM_FLOATS (W_TOTAL + SLOT_FLOATS)  // 28672
#define SMEM_BYTES (SMEM_FLOATS * 4)       // 114688 B -> 2 CTAs/SM (with 1KB/CTA reserve)

typedef unsigned long long ull;

__device__ __forceinline__ void ffma2(ull& d, ull a, ull b) {
    asm("fma.rn.f32x2 %0, %1, %2, %0;" : "+l"(d) : "l"(a), "l"(b));
}
__device__ __forceinline__ float pairsum(ull v) {
    float lo, hi;
    asm("mov.b64 {%0, %1}, %2;" : "=f"(lo), "=f"(hi) : "l"(v));
    return lo + hi;
}
__device__ __forceinline__ ull pack2(float lo, float hi) {
    ull r;
    asm("mov.b64 %0, {%1, %2};" : "=l"(r) : "f"(lo), "f"(hi));
    return r;
}
// Zero pair lanes per relu-mask bits (2q, 2q+1).
__device__ __forceinline__ ull maskpair(ull v, ull m, int q) {
    ull mm = (((m >> (2 * q)) & 1ull) * 0x00000000FFFFFFFFull)
           | (((m >> (2 * q + 1)) & 1ull) * 0xFFFFFFFF00000000ull);
    return v & mm;
}
// Swizzled float-offset of 64-bit pair q within a 64-float staging row.
// 16B-chunk c = q>>1 is XORed with rmask=(row&15); low half / high half via q&1.
__device__ __forceinline__ int st_pair_off(int rm, int q) {
    return (((q >> 1) ^ rm) << 2) + ((q & 1) << 1);
}

// ---------------------------------------------------------------------------
// Dual-row sequential matvec (cuBLAS-exact rounding). Per-row chain:
//   a = t*W[j][0]; k ascending fmaf; s = a + bias[j]  -- bit-identical to R3/R4.
// RELU=1: clamp + set mask bits (layers 0,1).  RELU=0: plain affine (layer 2).
// bias/c0 come from gmem via uniform __ldg (L1-cached broadcast).
// Outputs written to swizzled staging.
// ---------------------------------------------------------------------------
template <int RELU>
__device__ __forceinline__ void seq_dual(
    const float* __restrict__ Wf,      // [64][64] row-major smem
    const float* __restrict__ Wfull,   // gmem W [64][65] (for t-column)
    const float* __restrict__ bvec,    // gmem bias [64]
    float t,
    const float2* __restrict__ x0, const float2* __restrict__ x1,  // 32 f2 each (regs)
    float* __restrict__ st0, float* __restrict__ st1, int rm,
    ull& m0, ull& m1) {
#pragma unroll 2
    for (int jj = 0; jj < 64; jj += 2) {
        float c0a = __ldg(Wfull + jj * 65);
        float c0b = __ldg(Wfull + (jj + 1) * 65);
        float ba = __ldg(bvec + jj);
        float bb = __ldg(bvec + jj + 1);
        float a00 = t * c0a, a01 = t * c0b;
        float a10 = t * c0a, a11 = t * c0b;
        const float4* w0 = (const float4*)(Wf + jj * 64);
        const float4* w1 = (const float4*)(Wf + (jj + 1) * 64);
#pragma unroll
        for (int q = 0; q < 16; q++) {
            float4 v0 = w0[q];
            float4 v1 = w1[q];
            float2 xa0 = x0[2 * q], xb0 = x0[2 * q + 1];
            float2 xa1 = x1[2 * q], xb1 = x1[2 * q + 1];
            a00 = fmaf(xa0.x, v0.x, a00); a00 = fmaf(xa0.y, v0.y, a00);
            a00 = fmaf(xb0.x, v0.z, a00); a00 = fmaf(xb0.y, v0.w, a00);
            a01 = fmaf(xa0.x, v1.x, a01); a01 = fmaf(xa0.y, v1.y, a01);
            a01 = fmaf(xb0.x, v1.z, a01); a01 = fmaf(xb0.y, v1.w, a01);
            a10 = fmaf(xa1.x, v0.x, a10); a10 = fmaf(xa1.y, v0.y, a10);
            a10 = fmaf(xb1.x, v0.z, a10); a10 = fmaf(xb1.y, v0.w, a10);
            a11 = fmaf(xa1.x, v1.x, a11); a11 = fmaf(xa1.y, v1.y, a11);
            a11 = fmaf(xb1.x, v1.z, a11); a11 = fmaf(xb1.y, v1.w, a11);
        }
        float s00 = a00 + ba, s01 = a01 + bb;
        float s10 = a10 + ba, s11 = a11 + bb;
        if (RELU) {
            if (s00 > 0.0f) m0 |= (1ull << jj); else s00 = 0.0f;
            if (s01 > 0.0f) m0 |= (1ull << (jj + 1)); else s01 = 0.0f;
            if (s10 > 0.0f) m1 |= (1ull << jj); else s10 = 0.0f;
            if (s11 > 0.0f) m1 |= (1ull << (jj + 1)); else s11 = 0.0f;
        }
        int off = st_pair_off(rm, jj >> 1);
        *(ull*)(st0 + off) = pack2(s00, s01);
        *(ull*)(st1 + off) = pack2(s10, s11);
    }
}

// ---------------------------------------------------------------------------
// Dual-row FFMA2 dot matvec (continuous path, backward chain): out = W x.
// Inputs packed pairs in regs; outputs to swizzled staging.
// ---------------------------------------------------------------------------
__device__ __forceinline__ void dot_dual(
    const float* __restrict__ Wf,
    const ull* __restrict__ x0, const ull* __restrict__ x1,
    float* __restrict__ st0, float* __restrict__ st1, int rm) {
#pragma unroll 1
    for (int jj = 0; jj < 64; jj += 2) {
        ull a00 = 0ull, a01 = 0ull, a10 = 0ull, a11 = 0ull;
        const ulonglong2* w0 = (const ulonglong2*)(Wf + jj * 64);
        const ulonglong2* w1 = (const ulonglong2*)(Wf + (jj + 1) * 64);
#pragma unroll
        for (int q = 0; q < 16; q++) {
            ulonglong2 v0 = w0[q];
            ulonglong2 v1 = w1[q];
            ffma2(a00, v0.x, x0[2 * q]); ffma2(a00, v0.y, x0[2 * q + 1]);
            ffma2(a01, v1.x, x0[2 * q]); ffma2(a01, v1.y, x0[2 * q + 1]);
            ffma2(a10, v0.x, x1[2 * q]); ffma2(a10, v0.y, x1[2 * q + 1]);
            ffma2(a11, v1.x, x1[2 * q]); ffma2(a11, v1.y, x1[2 * q + 1]);
        }
        int off = st_pair_off(rm, jj >> 1);
        *(ull*)(st0 + off) = pack2(pairsum(a00), pairsum(a01));
        *(ull*)(st1 + off) = pack2(pairsum(a10), pairsum(a11));
    }
}

__global__ void __launch_bounds__(TPB, 2)
ode_kernel(const float* __restrict__ tptr, const float* __restrict__ z,
           const float* __restrict__ e,
           const float* __restrict__ W0, const float* __restrict__ b0,
           const float* __restrict__ W1, const float* __restrict__ b1,
           const float* __restrict__ W2, const float* __restrict__ b2,
           float* __restrict__ zdot, float* __restrict__ negdiv) {
    extern __shared__ float sm[];
    const int tid = threadIdx.x;

    // ---- Stage Wf per layer (row-major, t-column & bias stay in gmem) ----
    {
        const float* Wg[3] = {W0, W1, W2};
#pragma unroll
        for (int l = 0; l < 3; l++) {
            float* base = sm + l * WL;
            for (int idx = tid; idx < 4096; idx += TPB) {
                int j = idx >> 6, k = idx & 63;
                base[j * 64 + k] = Wg[l][j * 65 + 1 + k];
            }
        }
    }
    __syncthreads();

    const float t = __ldg(tptr);
    const int r0 = blockIdx.x * ROWS_CTA + tid;
    const int r1 = r0 + TPB;

    const float* L0 = sm;
    const float* L1 = sm + WL;
    const float* L2 = sm + 2 * WL;

    float* slot = sm + W_TOTAL;                 // 256 rows x 64 floats, swizzled
    float* st0 = slot + tid * 64;
    float* st1 = slot + (tid + TPB) * 64;
    const int rm = tid & 15;                     // (tid+128)&15 == tid&15: same swizzle

    ull mA0 = 0ull, mB0 = 0ull;   // relu masks layer0 (row0,row1)
    ull mA1 = 0ull, mB1 = 0ull;   // relu masks layer1

    // ---- Forward: 3 seq-style matvecs (L0/L1 mask-exact; L2 continuous) ----
    {
        float2 x0[32], x1[32];
        {
            const float4* zp0 = (const float4*)(z + (size_t)r0 * 64);
            const float4* zp1 = (const float4*)(z + (size_t)r1 * 64);
#pragma unroll
            for (int i = 0; i < 16; i++) {
                float4 v0 = zp0[i], v1 = zp1[i];
                x0[2 * i] = make_float2(v0.x, v0.y); x0[2 * i + 1] = make_float2(v0.z, v0.w);
                x1[2 * i] = make_float2(v1.x, v1.y); x1[2 * i + 1] = make_float2(v1.z, v1.w);
            }
        }
        seq_dual<1>(L0, W0, b0, t, x0, x1, st0, st1, rm, mA0, mB0);
#pragma unroll
        for (int q = 0; q < 32; q++) {
            int off = st_pair_off(rm, q);
            x0[q] = *(const float2*)(st0 + off);
            x1[q] = *(const float2*)(st1 + off);
        }
        seq_dual<1>(L1, W1, b1, t, x0, x1, st0, st1, rm, mA1, mB1);
#pragma unroll
        for (int q = 0; q < 32; q++) {
            int off = st_pair_off(rm, q);
            x0[q] = *(const float2*)(st0 + off);
            x1[q] = *(const float2*)(st1 + off);
        }
        ull d0 = 0ull, d1 = 0ull;  // unused masks
        seq_dual<0>(L2, W2, b2, t, x0, x1, st0, st1, rm, d0, d1);  // z_dot staged
    }

    // ---- Coalesced z_dot flush ----
    __syncthreads();
    {
        float4* dst = (float4*)(zdot + (size_t)blockIdx.x * ROWS_CTA * 64);
        for (int i4 = tid; i4 < ROWS_CTA * 16; i4 += TPB) {
            int r = i4 >> 4, c4 = i4 & 15;
            dst[i4] = *(const float4*)(slot + r * 64 + ((c4 ^ (r & 15)) << 2));
        }
    }
    __syncthreads();

    // ---- Backward: chain  u = W0c e ; D0 ; W1c ; D1 ; W2c ; dot with e ----
    {
        ull xp0[32], xp1[32];
        {
            const float4* e0 = (const float4*)(e + (size_t)r0 * 64);
            const float4* e1 = (const float4*)(e + (size_t)r1 * 64);
#pragma unroll
            for (int i = 0; i < 16; i++) {
                float4 v0 = e0[i], v1 = e1[i];
                xp0[2 * i] = pack2(v0.x, v0.y); xp0[2 * i + 1] = pack2(v0.z, v0.w);
                xp1[2 * i] = pack2(v1.x, v1.y); xp1[2 * i + 1] = pack2(v1.z, v1.w);
            }
        }
        dot_dual(L0, xp0, xp1, st0, st1, rm);                 // u
#pragma unroll
        for (int q = 0; q < 32; q++) {
            int off = st_pair_off(rm, q);
            xp0[q] = maskpair(*(const ull*)(st0 + off), mA0, q);
            xp1[q] = maskpair(*(const ull*)(st1 + off), mB0, q);
        }
        dot_dual(L1, xp0, xp1, st0, st1, rm);                 // y
#pragma unroll
        for (int q = 0; q < 32; q++) {
            int off = st_pair_off(rm, q);
            xp0[q] = maskpair(*(const ull*)(st0 + off), mA1, q);
            xp1[q] = maskpair(*(const ull*)(st1 + off), mB1, q);
        }
        dot_dual(L2, xp0, xp1, st0, st1, rm);                 // p (staged)

        // div = e . p   (e re-read; L2-resident from earlier read)
        ull dp0 = 0ull, dp1 = 0ull;
        {
            const float4* e0 = (const float4*)(e + (size_t)r0 * 64);
            const float4* e1 = (const float4*)(e + (size_t)r1 * 64);
#pragma unroll
            for (int i = 0; i < 16; i++) {
                float4 v0 = e0[i], v1 = e1[i];
                int offa = st_pair_off(rm, 2 * i);
                int offb = st_pair_off(rm, 2 * i + 1);
                ffma2(dp0, pack2(v0.x, v0.y), *(const ull*)(st0 + offa));
                ffma2(dp0, pack2(v0.z, v0.w), *(const ull*)(st0 + offb));
                ffma2(dp1, pack2(v1.x, v1.y), *(const ull*)(st1 + offa));
                ffma2(dp1, pack2(v1.z, v1.w), *(const ull*)(st1 + offb));
            }
        }
        negdiv[r0] = -pairsum(dp0);
        negdiv[r1] = -pairsum(dp1);
    }
}

extern "C" void kernel_launch(void* const* d_in, const int* in_sizes, int n_in,
                              void* d_out, int out_size) {
    const float* t  = (const float*)d_in[0];
    const float* z  = (const float*)d_in[1];
    const float* e  = (const float*)d_in[2];
    const float* W0 = (const float*)d_in[3];
    const float* b0 = (const float*)d_in[4];
    const float* W1 = (const float*)d_in[5];
    const float* b1 = (const float*)d_in[6];
    const float* W2 = (const float*)d_in[7];
    const float* b2 = (const float*)d_in[8];

    float* zdot = (float*)d_out;                       // [B, 64]
    float* negdiv = zdot + (size_t)B_TOTAL * 64;       // [B, 1]

    cudaFuncSetAttribute(ode_kernel, cudaFuncAttributeMaxDynamicSharedMemorySize, SMEM_BYTES);
    ode_kernel<<<NBLK, TPB, SMEM_BYTES>>>(t, z, e, W0, b0, W1, b1, W2, b2, zdot, negdiv);
}